// round 1
// baseline (speedup 1.0000x reference)
#include <cuda_runtime.h>

#define PH 7
#define PW 7
#define SP 4
#define CH 10
#define FH 34
#define FW 34
#define NPIX (FH * FW)      // 1156
#define PIX_PAD 1160        // padded plane stride in floats
#define NBINS (PH * PW)     // 49
#define TPB 256

// Shared layout: sm[c * PIX_PAD + pix]  (10 planes, 46.4 KB static)
__global__ void __launch_bounds__(TPB) psroi_kernel(
    const float* __restrict__ ft,     // (C*49, 34, 34)
    const float* __restrict__ rois,   // (N, 5)
    float* __restrict__ out,          // (N, C, 49)
    int N)
{
    __shared__ float sm[CH * PIX_PAD];

    const int bin = blockIdx.y;            // ph*7 + pw
    const int ph  = bin / PW;
    const int pw  = bin - ph * PW;
    const int tid = threadIdx.x;

    // ---- Stage the (ph,pw) slice for all 10 channels into smem (coalesced) ----
    {
        const float* base = ft + (size_t)bin * NPIX;
        #pragma unroll
        for (int c = 0; c < CH; ++c) {
            const float* src = base + (size_t)c * (NBINS * NPIX);
            for (int p = tid; p < NPIX; p += TPB)
                sm[c * PIX_PAD + p] = src[p];
        }
    }

    // ---- Per-roi setup (no smem needed; overlaps with fill) ----
    const int n = blockIdx.x * TPB + tid;
    const bool active = (n < N);

    float gy0 = 0.f, gy1 = 0.f, gy2 = 0.f;
    float gx0 = 0.f, gx1 = 0.f, gx2 = 0.f;
    int   y0i = 0, x0i = 0;
    float cnt = 0.f;

    if (active) {
        const float rsw = rois[n * 5 + 1] * 0.125f;
        const float rsh = rois[n * 5 + 2] * 0.125f;
        const float rew = rois[n * 5 + 3] * 0.125f;
        const float reh = rois[n * 5 + 4] * 0.125f;

        float roi_h = reh - rsh; if (!(roi_h > 0.1f)) roi_h = 0.1f;
        float roi_w = rew - rsw; if (!(roi_w > 0.1f)) roi_w = 0.1f;

        const float bin_h = __fdiv_rn(roi_h, 7.0f);
        const float bin_w = __fdiv_rn(roi_w, 7.0f);
        const float sub_h = 0.25f * bin_h;     // exact
        const float sub_w = 0.25f * bin_w;     // exact

        const float hstart = floorf(__fadd_rn(rsh, __fmul_rn((float)ph, bin_h)));
        const float wstart = floorf(__fadd_rn(rsw, __fmul_rn((float)pw, bin_w)));
        y0i = (int)hstart;
        x0i = (int)wstart;

        int cntH = 0, cntW = 0;

        #pragma unroll
        for (int s = 0; s < SP; ++s) {
            const float fs = (float)s + 0.5f;
            // ---- vertical sample ----
            {
                const float H = __fadd_rn(hstart, __fmul_rn(fs, sub_h));
                if (H > -1.0f && H < (float)FH) {
                    ++cntH;
                    const float yf = floorf(H);
                    const float dy = H - yf;
                    const int y1 = (int)yf;
                    const int j  = y1 - y0i;                 // in {0,1} by construction
                    const float w1 = (y1 >= 0 && y1 < FH)       ? (1.0f - dy) : 0.0f;
                    const float w2 = (y1 + 1 >= 0 && y1 + 1 < FH) ? dy          : 0.0f;
                    if (j == 0) { gy0 += w1; gy1 += w2; }
                    else        { gy1 += w1; gy2 += w2; }
                }
            }
            // ---- horizontal sample ----
            {
                const float W = __fadd_rn(wstart, __fmul_rn(fs, sub_w));
                if (W > -1.0f && W < (float)FW) {
                    ++cntW;
                    const float xf = floorf(W);
                    const float dx = W - xf;
                    const int x1 = (int)xf;
                    const int i  = x1 - x0i;                 // in {0,1}
                    const float w1 = (x1 >= 0 && x1 < FW)       ? (1.0f - dx) : 0.0f;
                    const float w2 = (x1 + 1 >= 0 && x1 + 1 < FW) ? dx          : 0.0f;
                    if (i == 0) { gx0 += w1; gx1 += w2; }
                    else        { gx1 += w1; gx2 += w2; }
                }
            }
        }
        cnt = (float)(cntH * cntW);
    }

    __syncthreads();

    if (!active) return;

    float acc[CH];
    #pragma unroll
    for (int c = 0; c < CH; ++c) acc[c] = 0.f;

    const float gys[3] = { gy0, gy1, gy2 };
    const float gxs[3] = { gx0, gx1, gx2 };

    if (cnt > 0.f) {
        const int rowbase = y0i * FW + x0i;
        #pragma unroll
        for (int j = 0; j < 3; ++j) {
            const float gyj = gys[j];
            if (gyj != 0.f) {
                const int off = rowbase + j * FW;
                #pragma unroll
                for (int i = 0; i < 3; ++i) {
                    const float w = gyj * gxs[i];
                    if (w != 0.f) {
                        const int pix = off + i;   // valid whenever weight != 0
                        #pragma unroll
                        for (int c = 0; c < CH; ++c)
                            acc[c] = fmaf(w, sm[c * PIX_PAD + pix], acc[c]);
                    }
                }
            }
        }
        const float inv = __fdiv_rn(1.0f, cnt);
        float* o = out + (size_t)n * (CH * NBINS) + bin;
        #pragma unroll
        for (int c = 0; c < CH; ++c)
            o[c * NBINS] = acc[c] * inv;
    } else {
        float* o = out + (size_t)n * (CH * NBINS) + bin;
        #pragma unroll
        for (int c = 0; c < CH; ++c)
            o[c * NBINS] = 0.f;
    }
}

extern "C" void kernel_launch(void* const* d_in, const int* in_sizes, int n_in,
                              void* d_out, int out_size)
{
    const float* ft   = (const float*)d_in[0];   // 490*34*34 floats
    const float* rois = (const float*)d_in[1];   // N*5 floats
    float* out        = (float*)d_out;           // N*10*49 floats

    const int N = in_sizes[1] / 5;

    dim3 grid((N + TPB - 1) / TPB, NBINS);
    psroi_kernel<<<grid, TPB>>>(ft, rois, out, N);
}

// round 2
// speedup vs baseline: 1.8929x; 1.8929x over previous
#include <cuda_runtime.h>
#include <cuda_fp16.h>

#define PH 7
#define PW 7
#define SP 4
#define CH 10
#define FH 34
#define FW 34
#define NPIX (FH * FW)      // 1156
#define NBINS (PH * PW)     // 49
#define TPB 256
#define RPT 4               // rois per thread
#define RPB (TPB * RPT)     // rois per block = 1024
#define PADC 16             // halves per pixel slot (10 used), 32B stride
#define SCRN 10240          // scratch column stride (max N)

// 490 x 10240 f32 scratch, layout scratch[(c*49+bin)*SCRN + n]  (~20 MB)
__device__ float g_scratch[CH * NBINS * SCRN];

__global__ void __launch_bounds__(TPB) psroi_kernel(
    const float* __restrict__ ft,     // (C*49, 34, 34)
    const float* __restrict__ rois,   // (N, 5)
    int N)
{
    __shared__ __align__(16) __half sm[NPIX * PADC];   // 36,992 B

    const int bin = blockIdx.y;            // ph*7 + pw
    const int ph  = bin / PW;
    const int pw  = bin - ph * PW;
    const int tid = threadIdx.x;

    // ---- Stage the (ph,pw) slice, all 10 channels, as fp16 [pix][c] ----
    {
        const float* base = ft + (size_t)bin * NPIX;
        for (int p = tid; p < NPIX; p += TPB) {
            unsigned int h2[5];
            #pragma unroll
            for (int c = 0; c < 5; ++c) {
                float a = base[(size_t)(2 * c)     * (NBINS * NPIX) + p];
                float b = base[(size_t)(2 * c + 1) * (NBINS * NPIX) + p];
                __half2 hh = __floats2half2_rn(a, b);
                h2[c] = *(unsigned int*)&hh;
            }
            uint4* dst = (uint4*)(sm + p * PADC);
            *dst = make_uint4(h2[0], h2[1], h2[2], h2[3]);
            *(unsigned int*)(sm + p * PADC + 8) = h2[4];
        }
    }
    __syncthreads();

    const int nbase = blockIdx.x * RPB + tid;

    #pragma unroll 1
    for (int r = 0; r < RPT; ++r) {
        const int n = nbase + r * TPB;
        if (n >= N) break;

        // ---- Per-roi separable weight setup (exact f32 ops, matches ref) ----
        const float rsw = rois[n * 5 + 1] * 0.125f;
        const float rsh = rois[n * 5 + 2] * 0.125f;
        const float rew = rois[n * 5 + 3] * 0.125f;
        const float reh = rois[n * 5 + 4] * 0.125f;

        float roi_h = reh - rsh; if (!(roi_h > 0.1f)) roi_h = 0.1f;
        float roi_w = rew - rsw; if (!(roi_w > 0.1f)) roi_w = 0.1f;

        const float bin_h = __fdiv_rn(roi_h, 7.0f);
        const float bin_w = __fdiv_rn(roi_w, 7.0f);
        const float sub_h = 0.25f * bin_h;
        const float sub_w = 0.25f * bin_w;

        const float hstart = floorf(__fadd_rn(rsh, __fmul_rn((float)ph, bin_h)));
        const float wstart = floorf(__fadd_rn(rsw, __fmul_rn((float)pw, bin_w)));
        const int y0i = (int)hstart;
        const int x0i = (int)wstart;

        float gy[3] = {0.f, 0.f, 0.f};
        float gx[3] = {0.f, 0.f, 0.f};
        int cntH = 0, cntW = 0;

        #pragma unroll
        for (int s = 0; s < SP; ++s) {
            const float fs = (float)s + 0.5f;
            {
                const float H = __fadd_rn(hstart, __fmul_rn(fs, sub_h));
                if (H > -1.0f && H < (float)FH) {
                    ++cntH;
                    const float yf = floorf(H);
                    const float dy = H - yf;
                    const int y1 = (int)yf;
                    const int j  = y1 - y0i;     // in {0,1}
                    const float w1 = (y1 >= 0 && y1 < FH)         ? (1.0f - dy) : 0.0f;
                    const float w2 = (y1 + 1 >= 0 && y1 + 1 < FH) ? dy          : 0.0f;
                    gy[j]     += w1;
                    gy[j + 1] += w2;
                }
            }
            {
                const float W = __fadd_rn(wstart, __fmul_rn(fs, sub_w));
                if (W > -1.0f && W < (float)FW) {
                    ++cntW;
                    const float xf = floorf(W);
                    const float dx = W - xf;
                    const int x1 = (int)xf;
                    const int i  = x1 - x0i;     // in {0,1}
                    const float w1 = (x1 >= 0 && x1 < FW)         ? (1.0f - dx) : 0.0f;
                    const float w2 = (x1 + 1 >= 0 && x1 + 1 < FW) ? dx          : 0.0f;
                    gx[i]     += w1;
                    gx[i + 1] += w2;
                }
            }
        }
        const float cnt = (float)(cntH * cntW);

        float acc[CH];
        #pragma unroll
        for (int c = 0; c < CH; ++c) acc[c] = 0.f;

        if (cnt > 0.f) {
            const int rowbase = y0i * FW + x0i;
            #pragma unroll
            for (int j = 0; j < 3; ++j) {
                const float gyj = gy[j];
                if (gyj != 0.f) {
                    const int off = rowbase + j * FW;
                    #pragma unroll
                    for (int i = 0; i < 3; ++i) {
                        const float w = gyj * gx[i];
                        if (w != 0.f) {
                            const __half* pp = sm + (off + i) * PADC;
                            const uint4 v = *(const uint4*)pp;
                            const unsigned int v4 = *(const unsigned int*)(pp + 8);
                            const float2 f0 = __half22float2(*(const __half2*)&v.x);
                            const float2 f1 = __half22float2(*(const __half2*)&v.y);
                            const float2 f2 = __half22float2(*(const __half2*)&v.z);
                            const float2 f3 = __half22float2(*(const __half2*)&v.w);
                            const float2 f4 = __half22float2(*(const __half2*)&v4);
                            acc[0] = fmaf(w, f0.x, acc[0]);
                            acc[1] = fmaf(w, f0.y, acc[1]);
                            acc[2] = fmaf(w, f1.x, acc[2]);
                            acc[3] = fmaf(w, f1.y, acc[3]);
                            acc[4] = fmaf(w, f2.x, acc[4]);
                            acc[5] = fmaf(w, f2.y, acc[5]);
                            acc[6] = fmaf(w, f3.x, acc[6]);
                            acc[7] = fmaf(w, f3.y, acc[7]);
                            acc[8] = fmaf(w, f4.x, acc[8]);
                            acc[9] = fmaf(w, f4.y, acc[9]);
                        }
                    }
                }
            }
            const float inv = __fdiv_rn(1.0f, cnt);
            #pragma unroll
            for (int c = 0; c < CH; ++c)
                g_scratch[(size_t)(c * NBINS + bin) * SCRN + n] = acc[c] * inv;
        } else {
            #pragma unroll
            for (int c = 0; c < CH; ++c)
                g_scratch[(size_t)(c * NBINS + bin) * SCRN + n] = 0.f;
        }
    }
}

// out[n*490 + q] = scratch[q*SCRN + n], q = c*49+bin  (tiled transpose)
__global__ void __launch_bounds__(256) transpose_kernel(
    float* __restrict__ out, int N)
{
    __shared__ float tile[32][33];
    const int tx = threadIdx.x;        // 0..31
    const int ty = threadIdx.y;        // 0..7
    const int qBase = blockIdx.y * 32;
    const int nBase = blockIdx.x * 32;

    #pragma unroll
    for (int r = ty; r < 32; r += 8) {
        const int q = qBase + r;
        const int n = nBase + tx;
        float v = 0.f;
        if (q < CH * NBINS && n < N)
            v = g_scratch[(size_t)q * SCRN + n];
        tile[r][tx] = v;
    }
    __syncthreads();
    #pragma unroll
    for (int r = ty; r < 32; r += 8) {
        const int n = nBase + r;
        const int q = qBase + tx;
        if (n < N && q < CH * NBINS)
            out[(size_t)n * (CH * NBINS) + q] = tile[tx][r];
    }
}

extern "C" void kernel_launch(void* const* d_in, const int* in_sizes, int n_in,
                              void* d_out, int out_size)
{
    const float* ft   = (const float*)d_in[0];   // 490*34*34 floats
    const float* rois = (const float*)d_in[1];   // N*5 floats
    float* out        = (float*)d_out;           // N*10*49 floats

    const int N = in_sizes[1] / 5;

    dim3 grid1((N + RPB - 1) / RPB, NBINS);
    psroi_kernel<<<grid1, TPB>>>(ft, rois, N);

    dim3 block2(32, 8);
    dim3 grid2((N + 31) / 32, (CH * NBINS + 31) / 32);
    transpose_kernel<<<grid2, block2>>>(out, N);
}